// round 12
// baseline (speedup 1.0000x reference)
#include <cuda_runtime.h>
#include <math.h>
#include <stdint.h>

// Problem dims
#define NR   512
#define DM   512
#define NH   8
#define HE   64
#define FF   2048
#define NL   6
#define MIX3 768

// 4x4 transpose within each 16-column group (self-inverse)
#define PCOL(d) (((d) & ~15) | (((d) & 3) << 2) | (((d) >> 2) & 3))

// ---------------- scratch (device globals; no allocation) ----------------
__device__ __align__(16) float g_h[NR * DM];      // fp32 residual (linear)
__device__ __align__(16) float g_ht[NR * DM];     // tf32-rounded, PCOL-permuted (GEMM A)
__device__ __align__(16) float g_attn[NR * DM];   // rounded+permuted (GEMM A)
__device__ __align__(16) float g_ffn[NR * FF];    // rounded+permuted (GEMM A)
__device__ __align__(16) float g_part[6 * NR * DM];

__device__ __forceinline__ float rtf(float x) {
    unsigned u;
    asm("cvt.rna.tf32.f32 %0, %1;" : "=r"(u) : "f"(x));
    return __uint_as_float(u);
}

// smem chunk swizzles (operate on word-address bits 2..4)
__device__ __forceinline__ int aswz(int g) {
    return ((g & 1) << 4) | (((g >> 1) & 3) << 2);
}
__device__ __forceinline__ int bswz(int n) {
    const int e = (n ^ (n >> 3)) & 7;
    return ((e & 1) << 4) | (((e >> 1) & 3) << 2);
}

// ---------------- embedding + positional concat ----------------
__global__ void embed_kernel(const int* __restrict__ x, const int* __restrict__ ip,
                             const float* __restrict__ emb, const float* __restrict__ pe) {
    int n = blockIdx.x;
    int d = threadIdx.x;
    int tok = x[n];
    int i   = ip[0];
    const float a = emb[tok * 256 + d];
    const float b = pe[i * 256 + d];
    g_h[n * DM + d]       = a;
    g_h[n * DM + 256 + d] = b;
    g_ht[n * DM + PCOL(d)]       = rtf(a);
    g_ht[n * DM + PCOL(256 + d)] = rtf(b);
}

// ---------------- TF32 tensor-core GEMM (cp.async + vectorized fragments) --
// Tile 64x64, BK=32, 256 threads = 8 warps (2m x 4n), warp tile 32x16.
// A gmem is PRE-ROUNDED and PCOL-permuted; cp.async, 3 stages.
// A smem: row*32 + ((chunk<<2) ^ aswz(row&7)) -> frag = 1 LDS.128 per row/16k.
// B smem: col*32 + (pos(k) ^ bswz(col)), pos = PCOL within 32; 2 buffers.

template <int ACT>   // 0 = none (+bias if non-null), 2 = bias+relu+round+PCOL out
__device__ __forceinline__ void gemm_body(
    const float* __restrict__ A, const float* __restrict__ B,
    const float* __restrict__ bias, float* __restrict__ C,
    int N, int K, int kStart, int kEnd, int m0, int n0)
{
    __shared__ __align__(16) float As[3][2048];
    __shared__ __align__(16) float Bs[2][2048];

    const int t    = threadIdx.x;
    const int warp = t >> 5;
    const int lane = t & 31;
    const int g    = lane >> 2;
    const int tg   = lane & 3;
    const int wm   = warp >> 2;       // 0..1 -> m offset 32*wm
    const int wn   = warp & 3;        // 0..3 -> n offset 16*wn

    const int ar = t >> 2;            // 0..63 A row
    const int c0 = t & 3;             // A chunk (and c0+4)
    const int bk  = t >> 4;           // 0..15 B k row
    const int bn4 = (t & 15) * 4;

    const int nt = (kEnd - kStart) >> 5;   // BK = 32

    const float* Ag = A + (size_t)(m0 + ar) * K + kStart;
    const float* Bg = B + (size_t)(kStart + bk) * N + n0 + bn4;

    const int aw0 = ar * 32 + ((c0 << 2) ^ aswz(ar & 7));
    const int aw1 = ar * 32 + (((c0 + 4) << 2) ^ aswz(ar & 7));
    const uint32_t aS0 = (uint32_t)__cvta_generic_to_shared(&As[0][aw0]);
    const uint32_t aS1 = (uint32_t)__cvta_generic_to_shared(&As[0][aw1]);
    const int posk = ((bk & 3) << 2) | ((bk >> 2) & 3);   // pos(bk); pos(bk+16)=posk|16

#define LOAD_A(kt, st) do {                                                        \
    const float* _s = Ag + (kt) * 32;                                              \
    asm volatile("cp.async.cg.shared.global [%0], [%1], 16;"                       \
                 :: "r"(aS0 + (uint32_t)(st) * 8192u), "l"(_s + c0 * 4));          \
    asm volatile("cp.async.cg.shared.global [%0], [%1], 16;"                       \
                 :: "r"(aS1 + (uint32_t)(st) * 8192u), "l"(_s + (c0 + 4) * 4));    \
} while (0)
#define CP_COMMIT() asm volatile("cp.async.commit_group;")
#define LDG_B(kt, r0, r1) do {                                                     \
    const float* _s = Bg + (size_t)(kt) * 32 * N;                                  \
    r0 = *(const float4*)_s;                                                       \
    r1 = *(const float4*)(_s + (size_t)16 * N);                                    \
} while (0)
#define STS_B(buf, r0, r1) do {                                                    \
    const float _q0[4] = {(r0).x, (r0).y, (r0).z, (r0).w};                         \
    const float _q1[4] = {(r1).x, (r1).y, (r1).z, (r1).w};                         \
    _Pragma("unroll")                                                              \
    for (int j = 0; j < 4; j++) {                                                  \
        const int n = bn4 + j;                                                     \
        const int bz = bswz(n);                                                    \
        Bs[buf][n * 32 + (posk ^ bz)]        = rtf(_q0[j]);                        \
        Bs[buf][n * 32 + ((posk | 16) ^ bz)] = rtf(_q1[j]);                        \
    }                                                                              \
} while (0)

    float c[2][2][4];
#pragma unroll
    for (int i = 0; i < 2; i++)
#pragma unroll
        for (int j = 0; j < 2; j++)
#pragma unroll
            for (int r = 0; r < 4; r++) c[i][j][r] = 0.f;

    // prologue
    float4 b0, b1, p0, p1;
    LDG_B(0, b0, b1);
    STS_B(0, b0, b1);
    if (nt > 1) LDG_B(1, b0, b1);
    LOAD_A(0, 0);
    CP_COMMIT();
    if (nt > 1) LOAD_A(1, 1);
    CP_COMMIT();

    // precomputed fragment addresses (word indices), G selects +16 XOR
    const int az = aswz(g);
    const int bz0 = bswz(wn * 16 + g);
    const int bz1 = bswz(wn * 16 + 8 + g);

    for (int kt = 0; kt < nt; kt++) {
        asm volatile("cp.async.wait_group 1;");
        __syncthreads();

        if (kt + 2 < nt) LOAD_A(kt + 2, (kt + 2) % 3);
        CP_COMMIT();
        if (kt + 2 < nt) LDG_B(kt + 2, p0, p1);

        const float* Ab = &As[kt % 3][0];
        const float* Bb = &Bs[kt & 1][0];

#pragma unroll
        for (int G = 0; G < 2; G++) {
            uint4 Af[2][2], Bf[2];
#pragma unroll
            for (int mt = 0; mt < 2; mt++)
#pragma unroll
                for (int rh = 0; rh < 2; rh++) {
                    const int row = wm * 32 + mt * 16 + rh * 8 + g;
                    Af[mt][rh] = *(const uint4*)&Ab[row * 32 + ((G * 16 + (tg << 2)) ^ az)];
                }
            Bf[0] = *(const uint4*)&Bb[(wn * 16 + g) * 32 + ((G * 16 + (tg << 2)) ^ bz0)];
            Bf[1] = *(const uint4*)&Bb[(wn * 16 + 8 + g) * 32 + ((G * 16 + (tg << 2)) ^ bz1)];

#pragma unroll
            for (int half = 0; half < 2; half++) {
#pragma unroll
                for (int mt = 0; mt < 2; mt++) {
                    const unsigned a0 = half ? Af[mt][0].z : Af[mt][0].x;
                    const unsigned a1 = half ? Af[mt][1].z : Af[mt][1].x;
                    const unsigned a2 = half ? Af[mt][0].w : Af[mt][0].y;
                    const unsigned a3 = half ? Af[mt][1].w : Af[mt][1].y;
#pragma unroll
                    for (int ntl = 0; ntl < 2; ntl++) {
                        const unsigned bb0 = half ? Bf[ntl].z : Bf[ntl].x;
                        const unsigned bb1 = half ? Bf[ntl].w : Bf[ntl].y;
                        asm volatile(
                            "mma.sync.aligned.m16n8k8.row.col.f32.tf32.tf32.f32 "
                            "{%0,%1,%2,%3}, {%4,%5,%6,%7}, {%8,%9}, {%0,%1,%2,%3};"
                            : "+f"(c[mt][ntl][0]), "+f"(c[mt][ntl][1]),
                              "+f"(c[mt][ntl][2]), "+f"(c[mt][ntl][3])
                            : "r"(a0), "r"(a1), "r"(a2), "r"(a3),
                              "r"(bb0), "r"(bb1));
                    }
                }
            }
        }

        if (kt + 1 < nt) STS_B((kt + 1) & 1, b0, b1);
        b0 = p0; b1 = p1;
    }
#undef LOAD_A
#undef CP_COMMIT
#undef LDG_B
#undef STS_B

    // epilogue: rows g/g+8, cols tg*2, tg*2+1
#pragma unroll
    for (int mt = 0; mt < 2; mt++) {
#pragma unroll
        for (int ntl = 0; ntl < 2; ntl++) {
#pragma unroll
            for (int half = 0; half < 2; half++) {
                const int row = m0 + wm * 32 + mt * 16 + g + half * 8;
                const int col = n0 + wn * 16 + ntl * 8 + tg * 2;
                float v0 = c[mt][ntl][half * 2 + 0];
                float v1 = c[mt][ntl][half * 2 + 1];
                if (bias) { v0 += bias[col]; v1 += bias[col + 1]; }
                if (ACT == 2) {
                    // A-arena output: relu + round + PCOL permute
                    const int pc = PCOL(col);
                    C[(size_t)row * N + pc]     = rtf(fmaxf(v0, 0.f));
                    C[(size_t)row * N + pc + 4] = rtf(fmaxf(v1, 0.f));
                } else {
                    float2 o = make_float2(v0, v1);
                    *(float2*)&C[(size_t)row * N + col] = o;
                }
            }
        }
    }
}

// Plain GEMM (full K); tile 64x64
template <int ACT>
__global__ __launch_bounds__(256, 2) void gemm_kernel(
    const float* __restrict__ A, const float* __restrict__ B,
    const float* __restrict__ bias, float* __restrict__ C, int N, int K)
{
    gemm_body<ACT>(A, B, bias, C, N, K, 0, K, blockIdx.y * 64, blockIdx.x * 64);
}

// Split-K GEMM: partials to Cp + z*NR*N
__global__ __launch_bounds__(256, 2) void gemm_splitk_kernel(
    const float* __restrict__ A, const float* __restrict__ B,
    float* __restrict__ Cp, int N, int K, int S)
{
    const int chunk = K / S;
    const int z = blockIdx.z;
    gemm_body<0>(A, B, nullptr, Cp + (size_t)z * NR * N,
                 N, K, z * chunk, (z + 1) * chunk, blockIdx.y * 64, blockIdx.x * 64);
}

// Fused QKV with split-K 2: z = which*2 + chunk, which: 0=Q 1=K 2=V
__global__ __launch_bounds__(256, 2) void gemm_qkv_splitk_kernel(
    const float* __restrict__ Wq, const float* __restrict__ Wk, const float* __restrict__ Wv,
    float* __restrict__ part, int l)
{
    const int z = blockIdx.z;
    const int which = z >> 1;
    const int chunk = z & 1;
    const float* W = ((which == 0) ? Wq : (which == 1) ? Wk : Wv) + (size_t)l * DM * DM;
    gemm_body<0>(g_ht, W, nullptr, part + (size_t)z * NR * DM,
                 DM, DM, chunk * 256, (chunk + 1) * 256, blockIdx.y * 64, blockIdx.x * 64);
}

// ---------------- split-K reduce + bias (pred head) ----------------
__global__ void reduce_bias_kernel(const float* __restrict__ part, int P,
                                   const float* __restrict__ bias,
                                   float* __restrict__ outp, int N)
{
    const int n = blockIdx.x;
    for (int c = threadIdx.x; c < N; c += blockDim.x) {
        float v = bias[c];
        for (int p = 0; p < P; p++)
            v += part[(size_t)p * NR * N + (size_t)n * N + c];
        outp[(size_t)n * N + c] = v;
    }
}

// ---------------- linear-attention: QKV reduce+bias+phi, state update ------
// part layout: z=0,1 Q partials; 2,3 K partials; 4,5 V partials
__global__ void attn_kernel(const float* __restrict__ part,
                            const float* __restrict__ bq, const float* __restrict__ bk,
                            const float* __restrict__ bv, int l,
                            const float* __restrict__ Si, const float* __restrict__ Zi,
                            float* __restrict__ S_out, float* __restrict__ Z_out)
{
    const int n = blockIdx.x;
    const int h = blockIdx.y;
    const int m = threadIdx.x;

    __shared__ float qs[HE], ks[HE], red[HE];

    const int baseqk = n * DM + h * HE;
    const size_t psz = (size_t)NR * DM;

    float qv = part[baseqk + m] + part[psz + baseqk + m] + bq[l * DM + h * HE + m];
    float kv = part[2 * psz + baseqk + m] + part[3 * psz + baseqk + m] + bk[l * DM + h * HE + m];
    const float vm = part[4 * psz + baseqk + m] + part[5 * psz + baseqk + m] + bv[l * DM + h * HE + m];

    qs[m] = (qv > 0.f) ? (qv + 1.f) : __expf(qv);
    ks[m] = (kv > 0.f) ? (kv + 1.f) : __expf(kv);

    const size_t zbase = ((size_t)n * NH + h) * HE;
    const float z = Zi[zbase + m] + ks[m];
    Z_out[zbase + m] = z;

    red[m] = qs[m] * z;
    __syncthreads();
#pragma unroll
    for (int s = 32; s > 0; s >>= 1) {
        if (m < s) red[m] += red[m + s];
        __syncthreads();
    }
    const float den = red[0] + 1e-6f;

    const size_t sbase = ((size_t)n * NH + h) * HE * HE;
    float num = 0.f;
#pragma unroll 8
    for (int e = 0; e < HE; e++) {
        float s = Si[sbase + (size_t)e * HE + m] + ks[e] * vm;
        S_out[sbase + (size_t)e * HE + m] = s;
        num = fmaf(qs[e], s, num);
    }
    g_attn[n * DM + PCOL(h * HE + m)] = rtf(num / den);   // A-arena: round+permute
}

// ---------------- residual + split-K reduce + bias + LayerNorm -----------
__global__ void add_ln_kernel(const float* __restrict__ part,
                              int P, const float* __restrict__ bias,
                              const float* __restrict__ g, const float* __restrict__ b)
{
    const int n = blockIdx.x;
    const int t = threadIdx.x;
    __shared__ float red[256];
    __shared__ float s_mean, s_rstd;

    float v0 = g_h[n * DM + t];
    float v1 = g_h[n * DM + 256 + t];
    for (int p = 0; p < P; p++) {
        v0 += part[(size_t)p * NR * DM + n * DM + t];
        v1 += part[(size_t)p * NR * DM + n * DM + 256 + t];
    }
    if (bias) { v0 += bias[t]; v1 += bias[256 + t]; }

    red[t] = v0 + v1;
    __syncthreads();
#pragma unroll
    for (int s = 128; s > 0; s >>= 1) {
        if (t < s) red[t] += red[t + s];
        __syncthreads();
    }
    if (t == 0) s_mean = red[0] * (1.f / DM);
    __syncthreads();
    const float mean = s_mean;

    float d0 = v0 - mean, d1 = v1 - mean;
    red[t] = d0 * d0 + d1 * d1;
    __syncthreads();
#pragma unroll
    for (int s = 128; s > 0; s >>= 1) {
        if (t < s) red[t] += red[t + s];
        __syncthreads();
    }
    if (t == 0) s_rstd = rsqrtf(red[0] * (1.f / DM) + 1e-5f);
    __syncthreads();
    const float rstd = s_rstd;

    const float o0 = d0 * rstd * g[t] + b[t];
    const float o1 = d1 * rstd * g[256 + t] + b[256 + t];
    g_h[n * DM + t]       = o0;
    g_h[n * DM + 256 + t] = o1;
    g_ht[n * DM + PCOL(t)]       = rtf(o0);
    g_ht[n * DM + PCOL(t + 256)] = rtf(o1);
}

// ---------------- host-side launch ----------------
extern "C" void kernel_launch(void* const* d_in, const int* in_sizes, int n_in,
                              void* d_out, int out_size)
{
    const int*   x      = (const int*)  d_in[0];
    const int*   ip     = (const int*)  d_in[1];
    const float* emb    = (const float*)d_in[2];
    const float* pe     = (const float*)d_in[3];
    const float* Wq     = (const float*)d_in[4];
    const float* bq     = (const float*)d_in[5];
    const float* Wk     = (const float*)d_in[6];
    const float* bk     = (const float*)d_in[7];
    const float* Wv     = (const float*)d_in[8];
    const float* bv     = (const float*)d_in[9];
    const float* Wo     = (const float*)d_in[10];
    const float* bo     = (const float*)d_in[11];
    const float* ln1_g  = (const float*)d_in[12];
    const float* ln1_b  = (const float*)d_in[13];
    const float* lin1_w = (const float*)d_in[14];
    const float* lin1_b = (const float*)d_in[15];
    const float* lin2_w = (const float*)d_in[16];
    const float* lin2_b = (const float*)d_in[17];
    const float* ln2_g  = (const float*)d_in[18];
    const float* ln2_b  = (const float*)d_in[19];
    const float* lnf_g  = (const float*)d_in[20];
    const float* lnf_b  = (const float*)d_in[21];
    const float* pred_w = (const float*)d_in[22];
    const float* pred_b = (const float*)d_in[23];
    const float* Si     = (const float*)d_in[24];
    const float* Zi     = (const float*)d_in[25];

    float* out = (float*)d_out;
    float* out_yhat = out;
    float* out_S    = out + (size_t)NR * MIX3;
    float* out_Z    = out_S + (size_t)NL * NR * NH * HE * HE;

    float *ht, *attn, *ffn, *part;
    cudaGetSymbolAddress((void**)&ht,   g_ht);
    cudaGetSymbolAddress((void**)&attn, g_attn);
    cudaGetSymbolAddress((void**)&ffn,  g_ffn);
    cudaGetSymbolAddress((void**)&part, g_part);

    embed_kernel<<<NR, 256>>>(x, ip, emb, pe);

    const dim3 gQKV(DM / 64, NR / 64, 6);      // 384 blocks (3 outputs x split-K 2)
    const dim3 gWo(DM / 64, NR / 64, 4);       // 256 blocks (split-K 4)
    const dim3 gF1(FF / 64, NR / 64);          // 256 blocks
    const dim3 gF2(DM / 64, NR / 64, 4);       // 256 blocks (split-K 4, chunk 512)
    const dim3 gPred(MIX3 / 64, NR / 64, 4);   // 384 blocks (split-K 4)
    const dim3 gAttn(NR, NH);

    const size_t ssz = (size_t)NR * NH * HE * HE;
    const size_t zsz = (size_t)NR * NH * HE;

    for (int l = 0; l < NL; l++) {
        gemm_qkv_splitk_kernel<<<gQKV, 256>>>(Wq, Wk, Wv, part, l);

        attn_kernel<<<gAttn, HE>>>(part, bq, bk, bv, l,
                                   Si + l * ssz, Zi + l * zsz,
                                   out_S + l * ssz, out_Z + l * zsz);

        gemm_splitk_kernel<<<gWo, 256>>>(attn, Wo + (size_t)l * DM * DM, part, DM, DM, 4);
        add_ln_kernel<<<NR, 256>>>(part, 4, bo + l * DM, ln1_g + l * DM, ln1_b + l * DM);

        gemm_kernel<2><<<gF1, 256>>>(ht, lin1_w + (size_t)l * DM * FF, lin1_b + l * FF,
                                     ffn, FF, DM);
        gemm_splitk_kernel<<<gF2, 256>>>(ffn, lin2_w + (size_t)l * FF * DM, part, DM, FF, 4);
        add_ln_kernel<<<NR, 256>>>(part, 4, lin2_b + l * DM, ln2_g + l * DM, ln2_b + l * DM);
    }

    add_ln_kernel<<<NR, 256>>>(nullptr, 0, nullptr, lnf_g, lnf_b);
    gemm_splitk_kernel<<<gPred, 256>>>(ht, pred_w, part, MIX3, DM, 4);
    reduce_bias_kernel<<<NR, 256>>>(part, 4, pred_b, out_yhat, MIX3);
}

// round 15
// speedup vs baseline: 1.0157x; 1.0157x over previous
#include <cuda_runtime.h>
#include <cuda_fp16.h>
#include <math.h>
#include <stdint.h>

// Problem dims
#define NR   512
#define DM   512
#define NH   8
#define HE   64
#define FF   2048
#define NL   6
#define MIX3 768

// ---------------- scratch (device globals; no allocation) ----------------
__device__ __align__(16) float  g_h[NR * DM];     // fp32 residual (linear)
__device__ __align__(16) __half g_ht[NR * DM];    // fp16 copy (GEMM A)
__device__ __align__(16) __half g_attn[NR * DM];  // fp16 (GEMM A)
__device__ __align__(16) __half g_ffn[NR * FF];   // fp16 (GEMM A)
__device__ __align__(16) float  g_part[6 * NR * DM];

// ---------------- embedding + positional concat ----------------
__global__ void embed_kernel(const int* __restrict__ x, const int* __restrict__ ip,
                             const float* __restrict__ emb, const float* __restrict__ pe) {
    int n = blockIdx.x;
    int d = threadIdx.x;
    int tok = x[n];
    int i   = ip[0];
    const float a = emb[tok * 256 + d];
    const float b = pe[i * 256 + d];
    g_h[n * DM + d]        = a;
    g_h[n * DM + 256 + d]  = b;
    g_ht[n * DM + d]       = __float2half_rn(a);
    g_ht[n * DM + 256 + d] = __float2half_rn(b);
}

// ---------------- FP16 tensor-core GEMM (cp.async pipelined) ----------
// Tile 64x64, BK=32, 256 threads = 8 warps (2m x 4n), warp tile 32x16.
// mma.m16n8k16.f16 with fp32 accum. A = fp16 gmem arena (cp.async, 3 stages).
// A smem: half2[row][16], phys h2 = h2 ^ (((row>>1)&3)<<2). 4KB/stage.
// B smem: half2[col][16], phys h2 = h2 ^ (((col>>1)&3)<<2). 2 buffers.
// B (fp32 weights) converted inline at STS.

template <int ACT>   // 0 = fp32 out (+bias if non-null), 2 = bias+relu -> fp16 out
__device__ __forceinline__ void gemm_body(
    const __half* __restrict__ A, const float* __restrict__ B,
    const float* __restrict__ bias, float* __restrict__ Cf, __half* __restrict__ Ch,
    int N, int K, int kStart, int kEnd, int m0, int n0)
{
    __shared__ __align__(16) __half2 As[3][1024];
    __shared__ __align__(16) __half2 Bs[2][1024];

    const int t    = threadIdx.x;
    const int warp = t >> 5;
    const int lane = t & 31;
    const int g    = lane >> 2;
    const int tg   = lane & 3;
    const int wm   = warp >> 2;       // 0..1 -> m offset 32*wm
    const int wn   = warp & 3;        // 0..3 -> n offset 16*wn

    const int ar = t >> 2;            // 0..63 A row
    const int ac = t & 3;             // A 16B chunk within row
    const int bk  = t >> 4;           // 0..15 B k row
    const int bn4 = (t & 15) * 4;

    const int nt = (kEnd - kStart) >> 5;   // BK = 32

    const __half* Ag = A + (size_t)(m0 + ar) * K + kStart;
    const float*  Bg = B + (size_t)(kStart + bk) * N + n0 + bn4;

    // A cp.async dst: chunk' = ac ^ ((ar>>1)&3), 4 half2 per chunk
    const uint32_t aS = (uint32_t)__cvta_generic_to_shared(
        &As[0][ar * 16 + ((ac ^ ((ar >> 1) & 3)) << 2)]);

#define LOAD_A(kt, st)                                                             \
    asm volatile("cp.async.cg.shared.global [%0], [%1], 16;"                       \
                 :: "r"(aS + (uint32_t)(st) * 4096u), "l"(Ag + (kt) * 32 + ac * 8))
#define CP_COMMIT() asm volatile("cp.async.commit_group;")
#define LDG_B(kt, r0, r1) do {                                                     \
    const float* _s = Bg + (size_t)(kt) * 32 * N;                                  \
    r0 = *(const float4*)_s;                                                       \
    r1 = *(const float4*)(_s + (size_t)16 * N);                                    \
} while (0)
#define STS_B(buf, r0, r1) do {                                                    \
    const float _q0[4] = {(r0).x, (r0).y, (r0).z, (r0).w};                         \
    const float _q1[4] = {(r1).x, (r1).y, (r1).z, (r1).w};                         \
    __half* _bh = (__half*)&Bs[buf][0];                                            \
    const int _h2 = bk >> 1, _lo = bk & 1;                                         \
    _Pragma("unroll")                                                              \
    for (int j = 0; j < 4; j++) {                                                  \
        const int n  = bn4 + j;                                                    \
        const int sw = ((n >> 1) & 3) << 2;                                        \
        _bh[(n * 16 + (_h2 ^ sw)) * 2 + _lo]       = __float2half_rn(_q0[j]);      \
        _bh[(n * 16 + ((_h2 + 8) ^ sw)) * 2 + _lo] = __float2half_rn(_q1[j]);      \
    }                                                                              \
} while (0)

    float c[2][2][4];
#pragma unroll
    for (int i = 0; i < 2; i++)
#pragma unroll
        for (int j = 0; j < 2; j++)
#pragma unroll
            for (int r = 0; r < 4; r++) c[i][j][r] = 0.f;

    // prologue
    float4 b0, b1, p0, p1;
    LDG_B(0, b0, b1);
    STS_B(0, b0, b1);
    if (nt > 1) LDG_B(1, b0, b1);
    LOAD_A(0, 0);
    CP_COMMIT();
    if (nt > 1) LOAD_A(1, 1);
    CP_COMMIT();

    const int asw  = ((g >> 1) & 3) << 2;
    const int col0 = wn * 16 + g;
    const int col1 = wn * 16 + 8 + g;
    const int bsw0 = ((col0 >> 1) & 3) << 2;
    const int bsw1 = ((col1 >> 1) & 3) << 2;

    for (int kt = 0; kt < nt; kt++) {
        asm volatile("cp.async.wait_group 1;");
        __syncthreads();

        if (kt + 2 < nt) LOAD_A(kt + 2, (kt + 2) % 3);
        CP_COMMIT();
        if (kt + 2 < nt) LDG_B(kt + 2, p0, p1);

        const __half2* Ab = &As[kt % 3][0];
        const __half2* Bb = &Bs[kt & 1][0];

#pragma unroll
        for (int step = 0; step < 2; step++) {
            const int h2a = step * 8 + tg;
            unsigned a[2][4];
#pragma unroll
            for (int mt = 0; mt < 2; mt++) {
                const int r0 = (wm * 32 + mt * 16 + g) * 16;
                const int r1 = r0 + 128;   // +8 rows
                a[mt][0] = *(const unsigned*)&Ab[r0 + (h2a ^ asw)];
                a[mt][1] = *(const unsigned*)&Ab[r1 + (h2a ^ asw)];
                a[mt][2] = *(const unsigned*)&Ab[r0 + ((h2a + 4) ^ asw)];
                a[mt][3] = *(const unsigned*)&Ab[r1 + ((h2a + 4) ^ asw)];
            }
            unsigned b[2][2];
            b[0][0] = *(const unsigned*)&Bb[col0 * 16 + (h2a ^ bsw0)];
            b[0][1] = *(const unsigned*)&Bb[col0 * 16 + ((h2a + 4) ^ bsw0)];
            b[1][0] = *(const unsigned*)&Bb[col1 * 16 + (h2a ^ bsw1)];
            b[1][1] = *(const unsigned*)&Bb[col1 * 16 + ((h2a + 4) ^ bsw1)];
#pragma unroll
            for (int mt = 0; mt < 2; mt++)
#pragma unroll
                for (int ntl = 0; ntl < 2; ntl++) {
                    asm volatile(
                        "mma.sync.aligned.m16n8k16.row.col.f32.f16.f16.f32 "
                        "{%0,%1,%2,%3}, {%4,%5,%6,%7}, {%8,%9}, {%0,%1,%2,%3};"
                        : "+f"(c[mt][ntl][0]), "+f"(c[mt][ntl][1]),
                          "+f"(c[mt][ntl][2]), "+f"(c[mt][ntl][3])
                        : "r"(a[mt][0]), "r"(a[mt][1]), "r"(a[mt][2]), "r"(a[mt][3]),
                          "r"(b[ntl][0]), "r"(b[ntl][1]));
                }
        }

        if (kt + 1 < nt) STS_B((kt + 1) & 1, b0, b1);
        b0 = p0; b1 = p1;
    }
#undef LOAD_A
#undef CP_COMMIT
#undef LDG_B
#undef STS_B

    // epilogue: rows g/g+8, cols tg*2, tg*2+1
#pragma unroll
    for (int mt = 0; mt < 2; mt++) {
#pragma unroll
        for (int ntl = 0; ntl < 2; ntl++) {
#pragma unroll
            for (int half = 0; half < 2; half++) {
                const int row = m0 + wm * 32 + mt * 16 + g + half * 8;
                const int col = n0 + wn * 16 + ntl * 8 + tg * 2;
                float v0 = c[mt][ntl][half * 2 + 0];
                float v1 = c[mt][ntl][half * 2 + 1];
                if (bias) { v0 += bias[col]; v1 += bias[col + 1]; }
                if (ACT == 2) {
                    __half2 hv = __floats2half2_rn(fmaxf(v0, 0.f), fmaxf(v1, 0.f));
                    *(__half2*)&Ch[(size_t)row * N + col] = hv;
                } else {
                    float2 o = make_float2(v0, v1);
                    *(float2*)&Cf[(size_t)row * N + col] = o;
                }
            }
        }
    }
}

// Plain GEMM (full K); ACT=2 writes fp16 arena
template <int ACT>
__global__ __launch_bounds__(256, 2) void gemm_kernel(
    const __half* __restrict__ A, const float* __restrict__ B,
    const float* __restrict__ bias, float* __restrict__ Cf, __half* __restrict__ Ch,
    int N, int K)
{
    gemm_body<ACT>(A, B, bias, Cf, Ch, N, K, 0, K, blockIdx.y * 64, blockIdx.x * 64);
}

// Split-K GEMM: partials to Cp + z*NR*N
__global__ __launch_bounds__(256, 2) void gemm_splitk_kernel(
    const __half* __restrict__ A, const float* __restrict__ B,
    float* __restrict__ Cp, int N, int K, int S)
{
    const int chunk = K / S;
    const int z = blockIdx.z;
    gemm_body<0>(A, B, nullptr, Cp + (size_t)z * NR * N, nullptr,
                 N, K, z * chunk, (z + 1) * chunk, blockIdx.y * 64, blockIdx.x * 64);
}

// Fused QKV with split-K 2: z = which*2 + chunk, which: 0=Q 1=K 2=V
__global__ __launch_bounds__(256, 2) void gemm_qkv_splitk_kernel(
    const float* __restrict__ Wq, const float* __restrict__ Wk, const float* __restrict__ Wv,
    float* __restrict__ part, int l)
{
    const int z = blockIdx.z;
    const int which = z >> 1;
    const int chunk = z & 1;
    const float* W = ((which == 0) ? Wq : (which == 1) ? Wk : Wv) + (size_t)l * DM * DM;
    gemm_body<0>(g_ht, W, nullptr, part + (size_t)z * NR * DM, nullptr,
                 DM, DM, chunk * 256, (chunk + 1) * 256, blockIdx.y * 64, blockIdx.x * 64);
}

// ---------------- split-K reduce + bias (pred head) ----------------
__global__ void reduce_bias_kernel(const float* __restrict__ part, int P,
                                   const float* __restrict__ bias,
                                   float* __restrict__ outp, int N)
{
    const int n = blockIdx.x;
    for (int c = threadIdx.x; c < N; c += blockDim.x) {
        float v = bias[c];
        for (int p = 0; p < P; p++)
            v += part[(size_t)p * NR * N + (size_t)n * N + c];
        outp[(size_t)n * N + c] = v;
    }
}

// ---------------- linear-attention: QKV reduce+bias+phi, state update ------
// part layout: z=0,1 Q partials; 2,3 K partials; 4,5 V partials
__global__ void attn_kernel(const float* __restrict__ part,
                            const float* __restrict__ bq, const float* __restrict__ bk,
                            const float* __restrict__ bv, int l,
                            const float* __restrict__ Si, const float* __restrict__ Zi,
                            float* __restrict__ S_out, float* __restrict__ Z_out)
{
    const int n = blockIdx.x;
    const int h = blockIdx.y;
    const int m = threadIdx.x;

    __shared__ float qs[HE], ks[HE], red[HE];

    const int baseqk = n * DM + h * HE;
    const size_t psz = (size_t)NR * DM;

    float qv = part[baseqk + m] + part[psz + baseqk + m] + bq[l * DM + h * HE + m];
    float kv = part[2 * psz + baseqk + m] + part[3 * psz + baseqk + m] + bk[l * DM + h * HE + m];
    const float vm = part[4 * psz + baseqk + m] + part[5 * psz + baseqk + m] + bv[l * DM + h * HE + m];

    qs[m] = (qv > 0.f) ? (qv + 1.f) : __expf(qv);
    ks[m] = (kv > 0.f) ? (kv + 1.f) : __expf(kv);

    const size_t zbase = ((size_t)n * NH + h) * HE;
    const float z = Zi[zbase + m] + ks[m];
    Z_out[zbase + m] = z;

    red[m] = qs[m] * z;
    __syncthreads();
#pragma unroll
    for (int s = 32; s > 0; s >>= 1) {
        if (m < s) red[m] += red[m + s];
        __syncthreads();
    }
    const float den = red[0] + 1e-6f;

    const size_t sbase = ((size_t)n * NH + h) * HE * HE;
    float num = 0.f;
#pragma unroll 8
    for (int e = 0; e < HE; e++) {
        float s = Si[sbase + (size_t)e * HE + m] + ks[e] * vm;
        S_out[sbase + (size_t)e * HE + m] = s;
        num = fmaf(qs[e], s, num);
    }
    g_attn[baseqk + m] = __float2half_rn(num / den);
}

// ---------------- residual + split-K reduce + bias + LayerNorm -----------
__global__ void add_ln_kernel(const float* __restrict__ part,
                              int P, const float* __restrict__ bias,
                              const float* __restrict__ g, const float* __restrict__ b)
{
    const int n = blockIdx.x;
    const int t = threadIdx.x;
    __shared__ float red[256];
    __shared__ float s_mean, s_rstd;

    float v0 = g_h[n * DM + t];
    float v1 = g_h[n * DM + 256 + t];
    for (int p = 0; p < P; p++) {
        v0 += part[(size_t)p * NR * DM + n * DM + t];
        v1 += part[(size_t)p * NR * DM + n * DM + 256 + t];
    }
    if (bias) { v0 += bias[t]; v1 += bias[256 + t]; }

    red[t] = v0 + v1;
    __syncthreads();
#pragma unroll
    for (int s = 128; s > 0; s >>= 1) {
        if (t < s) red[t] += red[t + s];
        __syncthreads();
    }
    if (t == 0) s_mean = red[0] * (1.f / DM);
    __syncthreads();
    const float mean = s_mean;

    float d0 = v0 - mean, d1 = v1 - mean;
    red[t] = d0 * d0 + d1 * d1;
    __syncthreads();
#pragma unroll
    for (int s = 128; s > 0; s >>= 1) {
        if (t < s) red[t] += red[t + s];
        __syncthreads();
    }
    if (t == 0) s_rstd = rsqrtf(red[0] * (1.f / DM) + 1e-5f);
    __syncthreads();
    const float rstd = s_rstd;

    const float o0 = d0 * rstd * g[t] + b[t];
    const float o1 = d1 * rstd * g[256 + t] + b[256 + t];
    g_h[n * DM + t]        = o0;
    g_h[n * DM + 256 + t]  = o1;
    g_ht[n * DM + t]       = __float2half_rn(o0);
    g_ht[n * DM + 256 + t] = __float2half_rn(o1);
}

// ---------------- host-side launch ----------------
extern "C" void kernel_launch(void* const* d_in, const int* in_sizes, int n_in,
                              void* d_out, int out_size)
{
    const int*   x      = (const int*)  d_in[0];
    const int*   ip     = (const int*)  d_in[1];
    const float* emb    = (const float*)d_in[2];
    const float* pe     = (const float*)d_in[3];
    const float* Wq     = (const float*)d_in[4];
    const float* bq     = (const float*)d_in[5];
    const float* Wk     = (const float*)d_in[6];
    const float* bk     = (const float*)d_in[7];
    const float* Wv     = (const float*)d_in[8];
    const float* bv     = (const float*)d_in[9];
    const float* Wo     = (const float*)d_in[10];
    const float* bo     = (const float*)d_in[11];
    const float* ln1_g  = (const float*)d_in[12];
    const float* ln1_b  = (const float*)d_in[13];
    const float* lin1_w = (const float*)d_in[14];
    const float* lin1_b = (const float*)d_in[15];
    const float* lin2_w = (const float*)d_in[16];
    const float* lin2_b = (const float*)d_in[17];
    const float* ln2_g  = (const float*)d_in[18];
    const float* ln2_b  = (const float*)d_in[19];
    const float* lnf_g  = (const float*)d_in[20];
    const float* lnf_b  = (const float*)d_in[21];
    const float* pred_w = (const float*)d_in[22];
    const float* pred_b = (const float*)d_in[23];
    const float* Si     = (const float*)d_in[24];
    const float* Zi     = (const float*)d_in[25];

    float* out = (float*)d_out;
    float* out_yhat = out;
    float* out_S    = out + (size_t)NR * MIX3;
    float* out_Z    = out_S + (size_t)NL * NR * NH * HE * HE;

    __half *ht, *attn, *ffn;
    float *part;
    cudaGetSymbolAddress((void**)&ht,   g_ht);
    cudaGetSymbolAddress((void**)&attn, g_attn);
    cudaGetSymbolAddress((void**)&ffn,  g_ffn);
    cudaGetSymbolAddress((void**)&part, g_part);

    embed_kernel<<<NR, 256>>>(x, ip, emb, pe);

    const dim3 gQKV(DM / 64, NR / 64, 6);      // 384 blocks (3 outputs x split-K 2)
    const dim3 gWo(DM / 64, NR / 64, 4);       // 256 blocks (split-K 4)
    const dim3 gF1(FF / 64, NR / 64);          // 256 blocks
    const dim3 gF2(DM / 64, NR / 64, 4);       // 256 blocks (split-K 4, chunk 512)
    const dim3 gPred(MIX3 / 64, NR / 64, 4);   // 384 blocks (split-K 4)
    const dim3 gAttn(NR, NH);

    const size_t ssz = (size_t)NR * NH * HE * HE;
    const size_t zsz = (size_t)NR * NH * HE;

    for (int l = 0; l < NL; l++) {
        gemm_qkv_splitk_kernel<<<gQKV, 256>>>(Wq, Wk, Wv, part, l);

        attn_kernel<<<gAttn, HE>>>(part, bq, bk, bv, l,
                                   Si + l * ssz, Zi + l * zsz,
                                   out_S + l * ssz, out_Z + l * zsz);

        gemm_splitk_kernel<<<gWo, 256>>>(attn, Wo + (size_t)l * DM * DM, part, DM, DM, 4);
        add_ln_kernel<<<NR, 256>>>(part, 4, bo + l * DM, ln1_g + l * DM, ln1_b + l * DM);

        gemm_kernel<2><<<gF1, 256>>>(ht, lin1_w + (size_t)l * DM * FF, lin1_b + l * FF,
                                     nullptr, ffn, FF, DM);
        gemm_splitk_kernel<<<gF2, 256>>>(ffn, lin2_w + (size_t)l * FF * DM, part, DM, FF, 4);
        add_ln_kernel<<<NR, 256>>>(part, 4, lin2_b + l * DM, ln2_g + l * DM, ln2_b + l * DM);
    }

    add_ln_kernel<<<NR, 256>>>(nullptr, 0, nullptr, lnf_g, lnf_b);
    gemm_splitk_kernel<<<gPred, 256>>>(ht, pred_w, part, MIX3, DM, 4);
    reduce_bias_kernel<<<NR, 256>>>(part, 4, pred_b, out_yhat, MIX3);
}